// round 7
// baseline (speedup 1.0000x reference)
#include <cuda_runtime.h>
#include <cuda_bf16.h>
#include <cstdint>

// Problem constants
constexpr int Bn  = 2;
constexpr int Ln  = 2048;
constexpr int Dn  = 1024;
constexpr int Hn  = 16;
constexpr int HDn = 64;
constexpr int NROW = Bn * Ln;   // 4096
constexpr size_t PLANE = (size_t)Bn * Hn * Ln * HDn;  // 4M elems

// Pre-split global scratch (bf16 stored as uint16)
__device__ uint16_t g_xh[(size_t)NROW * Dn];
__device__ uint16_t g_xl[(size_t)NROW * Dn];
__device__ uint16_t g_wh[(size_t)4 * Dn * Dn];   // slots: Wq,Wk,Wv,Wo
__device__ uint16_t g_wl[(size_t)4 * Dn * Dn];
__device__ uint16_t g_qkvh[3 * PLANE];           // [3][B][H][L][HD]
__device__ uint16_t g_qkvl[3 * PLANE];
__device__ uint16_t g_yh[(size_t)NROW * Dn];     // attn out, col = h*64+hd
__device__ uint16_t g_yl[(size_t)NROW * Dn];

// ---------------------------------------------------------------------------
// Helpers
// ---------------------------------------------------------------------------
__device__ __forceinline__ uint32_t s2u(const void* p) {
    uint32_t a;
    asm("{ .reg .u64 t; cvta.to.shared.u64 t, %1; cvt.u32.u64 %0, t; }"
        : "=r"(a) : "l"(p));
    return a;
}
__device__ __forceinline__ void cp16(uint32_t dst, const void* src) {
    asm volatile("cp.async.cg.shared.global [%0], [%1], 16;"
                 :: "r"(dst), "l"(src) : "memory");
}
#define CP_COMMIT() asm volatile("cp.async.commit_group;" ::: "memory")
#define CP_WAIT0()  asm volatile("cp.async.wait_group 0;" ::: "memory")
#define CP_WAIT1()  asm volatile("cp.async.wait_group 1;" ::: "memory")

__device__ __forceinline__ void ldm_x4(uint32_t* r, uint32_t a) {
    asm volatile("ldmatrix.sync.aligned.m8n8.x4.shared.b16 {%0,%1,%2,%3}, [%4];"
                 : "=r"(r[0]), "=r"(r[1]), "=r"(r[2]), "=r"(r[3]) : "r"(a));
}
__device__ __forceinline__ void ldm_x4t(uint32_t* r, uint32_t a) {
    asm volatile("ldmatrix.sync.aligned.m8n8.x4.trans.shared.b16 {%0,%1,%2,%3}, [%4];"
                 : "=r"(r[0]), "=r"(r[1]), "=r"(r[2]), "=r"(r[3]) : "r"(a));
}
__device__ __forceinline__ void mma_bf16(float* c, const uint32_t* a,
                                         const uint32_t* b) {
    asm volatile(
        "mma.sync.aligned.m16n8k16.row.col.f32.bf16.bf16.f32 "
        "{%0,%1,%2,%3}, {%4,%5,%6,%7}, {%8,%9}, {%0,%1,%2,%3};"
        : "+f"(c[0]), "+f"(c[1]), "+f"(c[2]), "+f"(c[3])
        : "r"(a[0]), "r"(a[1]), "r"(a[2]), "r"(a[3]), "r"(b[0]), "r"(b[1]));
}
__device__ __forceinline__ uint16_t bfu(float f) {
    __nv_bfloat16 h = __float2bfloat16_rn(f);
    return *(uint16_t*)&h;
}
__device__ __forceinline__ float bff(uint16_t u) {
    __nv_bfloat16 h = *(__nv_bfloat16*)&u;
    return __bfloat162float(h);
}
__device__ __forceinline__ void split4(float4 v, uint2& hi, uint2& lo) {
    uint16_t h0 = bfu(v.x), h1 = bfu(v.y), h2 = bfu(v.z), h3 = bfu(v.w);
    uint16_t l0 = bfu(v.x - bff(h0)), l1 = bfu(v.y - bff(h1));
    uint16_t l2 = bfu(v.z - bff(h2)), l3 = bfu(v.w - bff(h3));
    hi = make_uint2((uint32_t)h0 | ((uint32_t)h1 << 16),
                    (uint32_t)h2 | ((uint32_t)h3 << 16));
    lo = make_uint2((uint32_t)l0 | ((uint32_t)l1 << 16),
                    (uint32_t)l2 | ((uint32_t)l3 << 16));
}
__device__ __forceinline__ void packhl(float f0, float f1,
                                       uint32_t& h2, uint32_t& l2) {
    uint16_t h0 = bfu(f0), h1 = bfu(f1);
    uint16_t l0 = bfu(f0 - bff(h0)), l1 = bfu(f1 - bff(h1));
    h2 = (uint32_t)h0 | ((uint32_t)h1 << 16);
    l2 = (uint32_t)l0 | ((uint32_t)l1 << 16);
}

// ---------------------------------------------------------------------------
// One-shot split of x and all weights into bf16 hi/lo
// ---------------------------------------------------------------------------
__global__ void __launch_bounds__(256) split_kernel(
    const float* __restrict__ x,
    const float* __restrict__ Wq, const float* __restrict__ Wk,
    const float* __restrict__ Wv, const float* __restrict__ Wo)
{
    int i = blockIdx.x * blockDim.x + threadIdx.x;   // float4 index
    const float4* src;
    uint2 *dh, *dl;
    if (i < (1 << 20)) {
        src = (const float4*)x + i;
        dh = (uint2*)g_xh + i;
        dl = (uint2*)g_xl + i;
    } else {
        int j = i - (1 << 20);
        int slot = j >> 18;
        int off  = j & ((1 << 18) - 1);
        const float* w = (slot == 0) ? Wq : (slot == 1) ? Wk
                        : (slot == 2) ? Wv : Wo;
        src = (const float4*)w + off;
        dh = (uint2*)g_wh + ((size_t)slot << 18) + off;
        dl = (uint2*)g_wl + ((size_t)slot << 18) + off;
    }
    uint2 hi, lo;
    split4(*src, hi, lo);
    *dh = hi;
    *dl = lo;
}

// ---------------------------------------------------------------------------
// bf16-split GEMM v4: 128x64 CTA tile, 8 warps (4m x 2n), warp tile 32x32.
// 3-stage cp.async pipeline, wait_group 1, one barrier per iteration.
// Stage layout (bytes): Ah 0 (10240), Al 10240, Bh 20480 (4608), Bl 25088.
// Stage size 29696 B, 3 stages = 89088 B dynamic smem. 2 CTAs/SM.
// ---------------------------------------------------------------------------
constexpr int G_STAGE = 29696;
constexpr int GEMM_SMEM_BYTES = 3 * G_STAGE;

__global__ void __launch_bounds__(256, 2) gemm_mma_kernel(
    float* __restrict__ outp, int mode)
{
    extern __shared__ uint16_t smg[];
    const uint32_t sb = s2u(smg);

    const int tid  = threadIdx.x;
    const int lane = tid & 31;
    const int w    = tid >> 5;
    const int wm   = w & 3;         // 4 m-groups of 32
    const int wn   = w >> 2;        // 2 n-groups of 32
    const int col0 = blockIdx.x * 64;
    const int row0 = blockIdx.y * 128;
    const int z    = blockIdx.z;

    const uint16_t* Aph = (mode == 0) ? g_xh : g_yh;
    const uint16_t* Apl = (mode == 0) ? g_xl : g_yl;
    const int slot = (mode == 0) ? z : 3;
    const uint16_t* Wph = g_wh + ((size_t)slot << 20);
    const uint16_t* Wpl = g_wl + ((size_t)slot << 20);

    float C[2][4][4];
    #pragma unroll
    for (int mi = 0; mi < 2; mi++)
        #pragma unroll
        for (int ni = 0; ni < 4; ni++)
            #pragma unroll
            for (int q = 0; q < 4; q++) C[mi][ni][q] = 0.f;

    // cp.async issue of one k-stage into stage s_
    auto issue = [&](int c_, int s_) {
        uint32_t dstb = sb + (uint32_t)s_ * G_STAGE;
        int k0 = c_ * 32;
        #pragma unroll
        for (int i = 0; i < 4; i++) {
            int hil = i >> 1;
            int local = (i & 1) * 256 + tid;
            int r = local >> 2, cc = local & 3;
            uint32_t dst = dstb + hil * 10240u + (uint32_t)(r * 40 + cc * 8) * 2;
            const uint16_t* src = (hil ? Apl : Aph)
                                  + (size_t)(row0 + r) * Dn + k0 + cc * 8;
            cp16(dst, src);
        }
        #pragma unroll
        for (int i = 0; i < 2; i++) {
            int kk = tid >> 3, cc = tid & 7;
            uint32_t dst = dstb + 20480u + i * 4608u
                           + (uint32_t)(kk * 72 + cc * 8) * 2;
            const uint16_t* src = (i ? Wpl : Wph)
                                  + (size_t)(k0 + kk) * Dn + col0 + cc * 8;
            cp16(dst, src);
        }
    };

    issue(0, 0); CP_COMMIT();
    issue(1, 1); CP_COMMIT();

    int st = 0;
    for (int c = 0; c < 32; c++) {
        if (c < 31) CP_WAIT1(); else CP_WAIT0();
        __syncthreads();
        if (c + 2 < 32) {
            int st2 = st + 2; if (st2 >= 3) st2 -= 3;
            issue(c + 2, st2);
            CP_COMMIT();
        }
        const uint32_t stgb = sb + (uint32_t)st * G_STAGE;

        #pragma unroll
        for (int ks = 0; ks < 2; ks++) {
            uint32_t ahf[2][4], alf[2][4], bhf[4][2], blf[4][2];
            #pragma unroll
            for (int mi = 0; mi < 2; mi++) {
                uint32_t off = (uint32_t)((wm * 32 + mi * 16 + (lane & 15)) * 80
                                          + ks * 32 + ((lane >> 4) * 16));
                ldm_x4(ahf[mi], stgb + off);
                ldm_x4(alf[mi], stgb + 10240u + off);
            }
            #pragma unroll
            for (int g = 0; g < 2; g++) {
                uint32_t off = 20480u
                    + (uint32_t)((ks * 16 + (lane & 15)) * 144
                                 + (wn * 32 + g * 16 + ((lane >> 4) * 8)) * 2);
                uint32_t t[4];
                ldm_x4t(t, stgb + off);
                bhf[g*2][0] = t[0]; bhf[g*2][1] = t[1];
                bhf[g*2+1][0] = t[2]; bhf[g*2+1][1] = t[3];
                ldm_x4t(t, stgb + 4608u + off);
                blf[g*2][0] = t[0]; blf[g*2][1] = t[1];
                blf[g*2+1][0] = t[2]; blf[g*2+1][1] = t[3];
            }
            #pragma unroll
            for (int mi = 0; mi < 2; mi++)
                #pragma unroll
                for (int ni = 0; ni < 4; ni++) {
                    mma_bf16(C[mi][ni], ahf[mi], bhf[ni]);
                    mma_bf16(C[mi][ni], ahf[mi], blf[ni]);
                    mma_bf16(C[mi][ni], alf[mi], bhf[ni]);
                }
        }
        st = (st + 1 == 3) ? 0 : st + 1;
    }

    #pragma unroll
    for (int mi = 0; mi < 2; mi++)
        #pragma unroll
        for (int ni = 0; ni < 4; ni++) {
            int row = row0 + wm * 32 + mi * 16 + (lane >> 2);
            int col = col0 + wn * 32 + ni * 8 + (lane & 3) * 2;
            if (mode == 0) {
                uint16_t* qh = g_qkvh + (size_t)z * PLANE;
                uint16_t* ql = g_qkvl + (size_t)z * PLANE;
                float s = (z == 0) ? 0.125f : 1.f;
                int hh = col >> 6, hd = col & 63;
                #pragma unroll
                for (int half = 0; half < 2; half++) {
                    int r = row + half * 8;
                    int b = r >> 11, l = r & 2047;
                    size_t off = (((size_t)(b * Hn + hh) * Ln + l) << 6) + hd;
                    uint32_t hw, lw;
                    packhl(C[mi][ni][half*2] * s, C[mi][ni][half*2+1] * s, hw, lw);
                    *(uint32_t*)(qh + off) = hw;
                    *(uint32_t*)(ql + off) = lw;
                }
            } else {
                float2 v0 = make_float2(C[mi][ni][0], C[mi][ni][1]);
                float2 v1 = make_float2(C[mi][ni][2], C[mi][ni][3]);
                *(float2*)(outp + (size_t)row * Dn + col) = v0;
                *(float2*)(outp + (size_t)(row + 8) * Dn + col) = v1;
            }
        }
}

// ---------------------------------------------------------------------------
// Tensor-core flash attention v3: Q frags register-resident, KV triple-
// buffered via cp.async (wait_group 1). Q staged in stage-2 region before
// the loop (consumed into registers; ordered vs kt=0's issue by top barrier).
// Stage (bytes): KH 0 (9216), KL 9216, VH 18432, VL 27648; size 36864.
// ---------------------------------------------------------------------------
constexpr int QS = 72;                 // elems per row
constexpr int A_STAGE = 36864;         // bytes per stage
constexpr int ATTN_SMEM_BYTES = 3 * A_STAGE;   // 110,592

__global__ void __launch_bounds__(256) attn_kernel()
{
    extern __shared__ uint16_t smh[];
    const uint32_t sb = s2u(smh);

    const int qt   = blockIdx.x;
    const int h    = blockIdx.y;
    const int b    = blockIdx.z;
    const int tid  = threadIdx.x;
    const int lane = tid & 31;
    const int wid  = tid >> 5;
    const int r0   = wid * 16;

    const size_t base = ((size_t)(b * Hn + h) * Ln) * HDn;
    const uint16_t* qh_g = g_qkvh + base;
    const uint16_t* ql_g = g_qkvl + base;
    const uint16_t* kh_g = g_qkvh + PLANE + base;
    const uint16_t* kl_g = g_qkvl + PLANE + base;
    const uint16_t* vh_g = g_qkvh + 2 * PLANE + base;
    const uint16_t* vl_g = g_qkvl + 2 * PLANE + base;

    const int ktmax = 2 * qt + 2;

    auto issue_kv = [&](int kt_, int s_) {
        uint32_t dstb = sb + (uint32_t)s_ * A_STAGE;
        #pragma unroll
        for (int i = 0; i < 8; i++) {
            int p = i >> 1;
            int local = (i & 1) * 256 + tid;
            int r = local >> 3, cc = local & 7;
            uint32_t dst = dstb + p * 9216u + (uint32_t)(r * QS + cc * 8) * 2;
            const uint16_t* gp = (p == 0) ? kh_g : (p == 1) ? kl_g
                                : (p == 2) ? vh_g : vl_g;
            cp16(dst, gp + (size_t)(kt_ * 64 + r) * HDn + cc * 8);
        }
    };

    issue_kv(0, 0); CP_COMMIT();
    issue_kv(1, 1); CP_COMMIT();   // ktmax >= 2 always

    // Load Q tile [128][64] hi/lo into stage-2 region (elem offsets
    // QH: 36864, QL: 46080), then extract fragments to registers.
    #pragma unroll
    for (int i = 0; i < 4; i++) {
        int idx = tid + i * 256;
        int r = idx >> 3, c8 = idx & 7;
        size_t go = (size_t)(qt * 128 + r) * HDn + c8 * 8;
        *(uint4*)(smh + 36864 + r * QS + c8 * 8) = *(const uint4*)(qh_g + go);
        *(uint4*)(smh + 46080 + r * QS + c8 * 8) = *(const uint4*)(ql_g + go);
    }
    __syncthreads();

    uint32_t qfh[4][4], qfl[4][4];
    #pragma unroll
    for (int ks = 0; ks < 4; ks++) {
        uint32_t qaddr = sb + (uint32_t)((36864 + (r0 + (lane & 15)) * QS
                          + ks * 16 + ((lane >> 4) * 8)) * 2);
        ldm_x4(qfh[ks], qaddr);
        ldm_x4(qfl[ks], qaddr + 9216u * 2);
    }

    float m0 = -1e30f, m1 = -1e30f, l0 = 0.f, l1 = 0.f;
    float O[8][4];
    #pragma unroll
    for (int nt = 0; nt < 8; nt++)
        #pragma unroll
        for (int q = 0; q < 4; q++) O[nt][q] = 0.f;

    const int qbase = qt * 128 + r0;

    int st = 0;
    for (int kt = 0; kt < ktmax; kt++) {
        if (kt + 1 < ktmax) CP_WAIT1(); else CP_WAIT0();
        __syncthreads();   // also orders Q extraction before stage-2 reuse
        if (kt + 2 < ktmax) {
            int st2 = st + 2; if (st2 >= 3) st2 -= 3;
            issue_kv(kt + 2, st2);
            CP_COMMIT();
        }
        const uint32_t stgb = sb + (uint32_t)st * A_STAGE;
        st = (st + 1 == 3) ? 0 : st + 1;

        if (kt * 64 > qbase + 15) continue;

        // ---- S = Q * K^T (3-pass split) ----
        float S[8][4];
        #pragma unroll
        for (int nt = 0; nt < 8; nt++)
            #pragma unroll
            for (int q = 0; q < 4; q++) S[nt][q] = 0.f;

        #pragma unroll
        for (int ks = 0; ks < 4; ks++) {
            #pragma unroll
            for (int ntp = 0; ntp < 4; ntp++) {
                uint32_t kaddr = stgb + (uint32_t)(((ntp * 16 + (lane & 7)
                                  + ((lane >> 4) << 3)) * QS
                                  + ((lane >> 3) & 1) * 8 + ks * 16) * 2);
                uint32_t bh[4], bl[4];
                ldm_x4(bh, kaddr);            // KH
                ldm_x4(bl, kaddr + 9216u);    // KL
                mma_bf16(S[2*ntp],   qfh[ks], bh);
                mma_bf16(S[2*ntp],   qfh[ks], bl);
                mma_bf16(S[2*ntp],   qfl[ks], bh);
                mma_bf16(S[2*ntp+1], qfh[ks], bh + 2);
                mma_bf16(S[2*ntp+1], qfh[ks], bl + 2);
                mma_bf16(S[2*ntp+1], qfl[ks], bh + 2);
            }
        }

        // ---- causal mask (diagonal tiles only) ----
        if (kt * 64 + 63 > qbase) {
            int q0 = qbase + (lane >> 2);
            int q1 = q0 + 8;
            #pragma unroll
            for (int nt = 0; nt < 8; nt++) {
                int k0 = kt * 64 + nt * 8 + (lane & 3) * 2;
                if (k0     > q0) S[nt][0] = -1e30f;
                if (k0 + 1 > q0) S[nt][1] = -1e30f;
                if (k0     > q1) S[nt][2] = -1e30f;
                if (k0 + 1 > q1) S[nt][3] = -1e30f;
            }
        }

        // ---- online softmax ----
        float mx0 = -1e30f, mx1 = -1e30f;
        #pragma unroll
        for (int nt = 0; nt < 8; nt++) {
            mx0 = fmaxf(mx0, fmaxf(S[nt][0], S[nt][1]));
            mx1 = fmaxf(mx1, fmaxf(S[nt][2], S[nt][3]));
        }
        mx0 = fmaxf(mx0, __shfl_xor_sync(0xffffffffu, mx0, 1));
        mx0 = fmaxf(mx0, __shfl_xor_sync(0xffffffffu, mx0, 2));
        mx1 = fmaxf(mx1, __shfl_xor_sync(0xffffffffu, mx1, 1));
        mx1 = fmaxf(mx1, __shfl_xor_sync(0xffffffffu, mx1, 2));
        float nm0 = fmaxf(m0, mx0), nm1 = fmaxf(m1, mx1);
        float c0 = __expf(m0 - nm0), c1 = __expf(m1 - nm1);
        float s0 = 0.f, s1 = 0.f;
        #pragma unroll
        for (int nt = 0; nt < 8; nt++) {
            S[nt][0] = __expf(S[nt][0] - nm0);
            S[nt][1] = __expf(S[nt][1] - nm0);
            S[nt][2] = __expf(S[nt][2] - nm1);
            S[nt][3] = __expf(S[nt][3] - nm1);
            s0 += S[nt][0] + S[nt][1];
            s1 += S[nt][2] + S[nt][3];
        }
        s0 += __shfl_xor_sync(0xffffffffu, s0, 1);
        s0 += __shfl_xor_sync(0xffffffffu, s0, 2);
        s1 += __shfl_xor_sync(0xffffffffu, s1, 1);
        s1 += __shfl_xor_sync(0xffffffffu, s1, 2);
        m0 = nm0; m1 = nm1;
        l0 = l0 * c0 + s0;
        l1 = l1 * c1 + s1;
        #pragma unroll
        for (int nt = 0; nt < 8; nt++) {
            O[nt][0] *= c0; O[nt][1] *= c0;
            O[nt][2] *= c1; O[nt][3] *= c1;
        }

        // ---- O += P * V (3-pass split) ----
        #pragma unroll
        for (int g = 0; g < 4; g++) {
            uint32_t ah[4], al[4];
            packhl(S[2*g][0],   S[2*g][1],   ah[0], al[0]);
            packhl(S[2*g][2],   S[2*g][3],   ah[1], al[1]);
            packhl(S[2*g+1][0], S[2*g+1][1], ah[2], al[2]);
            packhl(S[2*g+1][2], S[2*g+1][3], ah[3], al[3]);
            #pragma unroll
            for (int ntp = 0; ntp < 4; ntp++) {
                uint32_t vaddr = stgb + 18432u
                    + (uint32_t)(((g * 16 + (lane & 15)) * QS
                                  + ntp * 16 + ((lane >> 4) << 3)) * 2);
                uint32_t vh[4], vl[4];
                ldm_x4t(vh, vaddr);            // VH
                ldm_x4t(vl, vaddr + 9216u);    // VL
                mma_bf16(O[2*ntp],   ah, vh);
                mma_bf16(O[2*ntp],   ah, vl);
                mma_bf16(O[2*ntp],   al, vh);
                mma_bf16(O[2*ntp+1], ah, vh + 2);
                mma_bf16(O[2*ntp+1], ah, vl + 2);
                mma_bf16(O[2*ntp+1], al, vh + 2);
            }
        }
    }

    // Finalize: pack to bf16 hi/lo and store y
    float il0 = 1.f / l0, il1 = 1.f / l1;
    int rowg = qt * 128 + r0 + (lane >> 2);
    #pragma unroll
    for (int nt = 0; nt < 8; nt++) {
        int hd = nt * 8 + (lane & 3) * 2;
        size_t o0 = (size_t)(b * Ln + rowg) * Dn + h * 64 + hd;
        size_t o1 = (size_t)(b * Ln + rowg + 8) * Dn + h * 64 + hd;
        uint32_t hw, lw;
        packhl(O[nt][0] * il0, O[nt][1] * il0, hw, lw);
        *(uint32_t*)(g_yh + o0) = hw;
        *(uint32_t*)(g_yl + o0) = lw;
        packhl(O[nt][2] * il1, O[nt][3] * il1, hw, lw);
        *(uint32_t*)(g_yh + o1) = hw;
        *(uint32_t*)(g_yl + o1) = lw;
    }
}

// ---------------------------------------------------------------------------
extern "C" void kernel_launch(void* const* d_in, const int* in_sizes, int n_in,
                              void* d_out, int out_size)
{
    (void)in_sizes; (void)n_in; (void)out_size;
    const float* x  = (const float*)d_in[0];
    const float* Wq = (const float*)d_in[1];
    const float* Wk = (const float*)d_in[2];
    const float* Wv = (const float*)d_in[3];
    const float* Wo = (const float*)d_in[4];
    float* out = (float*)d_out;

    cudaFuncSetAttribute(gemm_mma_kernel,
                         cudaFuncAttributeMaxDynamicSharedMemorySize,
                         GEMM_SMEM_BYTES);
    cudaFuncSetAttribute(attn_kernel,
                         cudaFuncAttributeMaxDynamicSharedMemorySize,
                         ATTN_SMEM_BYTES);

    split_kernel<<<8192, 256>>>(x, Wq, Wk, Wv, Wo);
    gemm_mma_kernel<<<dim3(Dn/64, NROW/128, 3), 256, GEMM_SMEM_BYTES>>>(nullptr, 0);
    attn_kernel<<<dim3(Ln/128, Hn, Bn), 256, ATTN_SMEM_BYTES>>>();
    gemm_mma_kernel<<<dim3(Dn/64, NROW/128, 1), 256, GEMM_SMEM_BYTES>>>(out, 1);
}